// round 1
// baseline (speedup 1.0000x reference)
#include <cuda_runtime.h>
#include <cstdint>

// ---------------- problem constants ----------------
// B=16, S=4096, C=1024, H=16, dh=64, L=77, Ce=768
#define BATCH   16
#define SEQ     4096
#define CDIM    1024
#define NHEAD   16
#define DHEAD   64
#define LTOK    77
#define CENC    768

#define MQ      (BATCH*SEQ)      // 65536
#define MKV     (BATCH*LTOK)     // 1232

// ---------------- scratch (no allocations allowed) ----------------
__device__ float g_q[(size_t)MQ * CDIM];     // 268 MB
__device__ float g_attn[(size_t)MQ * CDIM];  // 268 MB
__device__ float g_k[(size_t)MKV * CDIM];
__device__ float g_v[(size_t)MKV * CDIM];

// ---------------- TF32 helpers ----------------
__device__ __forceinline__ unsigned f2tf32(float x) {
    unsigned r;
    asm("cvt.rna.tf32.f32 %0, %1;" : "=r"(r) : "f"(x));
    return r;
}

// ============================================================
// Generic TF32 tensor-core GEMM: C[M,N] = A[M,K] @ B[K,N] (+bias)
// Row-major A, B, C. K % 16 == 0, N % 128 == 0. M may be ragged.
// Block tile 128x128x16, 256 threads, 8 warps (2m x 4n), warp tile 64x32,
// mma.m16n8k8 tf32, fp32 accumulate.
// ============================================================
#define PA 136
#define PB 136

__global__ void __launch_bounds__(256, 2) gemm_tf32(
    const float* __restrict__ A, const float* __restrict__ B,
    float* __restrict__ C, int M, int K, int N,
    const float* __restrict__ bias)
{
    __shared__ unsigned As[16 * PA];
    __shared__ unsigned Bs[16 * PB];

    const int t    = threadIdx.x;
    const int m0   = blockIdx.y * 128;
    const int n0   = blockIdx.x * 128;
    const int lane = t & 31;
    const int wid  = t >> 5;
    const int wm   = (wid >> 2) * 64;   // 0 or 64
    const int wn   = (wid & 3) * 32;    // 0,32,64,96
    const int gid  = lane >> 2;         // 0..7
    const int tg   = lane & 3;          // 0..3

    float acc[4][4][4];
#pragma unroll
    for (int i = 0; i < 4; i++)
#pragma unroll
        for (int j = 0; j < 4; j++)
#pragma unroll
            for (int r = 0; r < 4; r++) acc[i][j][r] = 0.f;

    for (int kt = 0; kt < K; kt += 16) {
        // --- load A tile (128m x 16k), store k-major As[k][m] ---
#pragma unroll
        for (int i = 0; i < 2; i++) {
            int f  = t + i * 256;      // 0..511 float4 slots
            int m  = f >> 2;           // 0..127
            int kq = (f & 3) << 2;     // 0,4,8,12
            float4 val = make_float4(0.f, 0.f, 0.f, 0.f);
            int grow = m0 + m;
            if (grow < M)
                val = *(const float4*)(A + (size_t)grow * K + kt + kq);
            As[(kq + 0) * PA + m] = f2tf32(val.x);
            As[(kq + 1) * PA + m] = f2tf32(val.y);
            As[(kq + 2) * PA + m] = f2tf32(val.z);
            As[(kq + 3) * PA + m] = f2tf32(val.w);
        }
        // --- load B tile (16k x 128n), natural Bs[k][n] ---
#pragma unroll
        for (int i = 0; i < 2; i++) {
            int f  = t + i * 256;
            int kr = f >> 5;           // 0..15
            int nq = (f & 31) << 2;    // 0..124
            float4 val = *(const float4*)(B + (size_t)(kt + kr) * N + n0 + nq);
            uint4 w;
            w.x = f2tf32(val.x); w.y = f2tf32(val.y);
            w.z = f2tf32(val.z); w.w = f2tf32(val.w);
            *(uint4*)(&Bs[kr * PB + nq]) = w;
        }
        __syncthreads();

#pragma unroll
        for (int kk = 0; kk < 16; kk += 8) {
            unsigned a[4][4], bf[4][2];
#pragma unroll
            for (int mf = 0; mf < 4; mf++) {
                int mb = wm + mf * 16 + gid;
                a[mf][0] = As[(kk + tg) * PA + mb];
                a[mf][1] = As[(kk + tg) * PA + mb + 8];
                a[mf][2] = As[(kk + tg + 4) * PA + mb];
                a[mf][3] = As[(kk + tg + 4) * PA + mb + 8];
            }
#pragma unroll
            for (int nf = 0; nf < 4; nf++) {
                int nb = wn + nf * 8 + gid;
                bf[nf][0] = Bs[(kk + tg) * PB + nb];
                bf[nf][1] = Bs[(kk + tg + 4) * PB + nb];
            }
#pragma unroll
            for (int mf = 0; mf < 4; mf++)
#pragma unroll
                for (int nf = 0; nf < 4; nf++)
                    asm volatile(
                        "mma.sync.aligned.m16n8k8.row.col.f32.tf32.tf32.f32 "
                        "{%0,%1,%2,%3}, {%4,%5,%6,%7}, {%8,%9}, {%0,%1,%2,%3};"
                        : "+f"(acc[mf][nf][0]), "+f"(acc[mf][nf][1]),
                          "+f"(acc[mf][nf][2]), "+f"(acc[mf][nf][3])
                        : "r"(a[mf][0]), "r"(a[mf][1]),
                          "r"(a[mf][2]), "r"(a[mf][3]),
                          "r"(bf[nf][0]), "r"(bf[nf][1]));
        }
        __syncthreads();
    }

    // --- epilogue ---
#pragma unroll
    for (int mf = 0; mf < 4; mf++) {
#pragma unroll
        for (int nf = 0; nf < 4; nf++) {
            int row = m0 + wm + mf * 16 + gid;
            int col = n0 + wn + nf * 8 + tg * 2;
            float b0 = 0.f, b1 = 0.f;
            if (bias) { b0 = bias[col]; b1 = bias[col + 1]; }
            if (row < M) {
                float2 r0 = make_float2(acc[mf][nf][0] + b0, acc[mf][nf][1] + b1);
                *(float2*)(C + (size_t)row * N + col) = r0;
            }
            if (row + 8 < M) {
                float2 r1 = make_float2(acc[mf][nf][2] + b0, acc[mf][nf][3] + b1);
                *(float2*)(C + (size_t)(row + 8) * N + col) = r1;
            }
        }
    }
}

// ============================================================
// Fused cross-attention: per (b,h) head, K/V (77x64) in smem,
// 256 query rows per block (one per thread), single-pass softmax
// (scores are O(1), no max-subtraction needed — exp never overflows).
// ============================================================
#define TILE_S 256
#define KV_F4  (LTOK * (DHEAD / 4))          // 77*16 float4
#define ATTN_SMEM ((2 * LTOK * DHEAD + TILE_S * DHEAD) * (int)sizeof(float))

__global__ void __launch_bounds__(TILE_S) attn_kernel(
    const float* __restrict__ q, const float* __restrict__ k,
    const float* __restrict__ v, float* __restrict__ o)
{
    extern __shared__ float sm[];
    float* Ks = sm;                        // 77*64
    float* Vs = Ks + LTOK * DHEAD;         // 77*64
    float* Qs = Vs + LTOK * DHEAD;         // 256*64, xor-swizzled float4

    const int bh = blockIdx.y;
    const int b  = bh >> 4;
    const int h  = bh & 15;
    const int s0 = blockIdx.x * TILE_S;
    const int t  = threadIdx.x;

    // load K, V head slices (coalesced)
    const float* kbase = k + (size_t)(b * LTOK) * CDIM + h * DHEAD;
    const float* vbase = v + (size_t)(b * LTOK) * CDIM + h * DHEAD;
    for (int i = t; i < KV_F4; i += TILE_S) {
        int j = i >> 4, c = i & 15;
        ((float4*)Ks)[j * 16 + c] = *(const float4*)(kbase + (size_t)j * CDIM + c * 4);
        ((float4*)Vs)[j * 16 + c] = *(const float4*)(vbase + (size_t)j * CDIM + c * 4);
    }
    // load Q tile, swizzle chunk index by (row & 7) for conflict-free reads
    const float* qbase = q + (size_t)(b * SEQ + s0) * CDIM + h * DHEAD;
    for (int f = t; f < TILE_S * 16; f += TILE_S) {
        int r = f >> 4, c = f & 15;
        float4 val = *(const float4*)(qbase + (size_t)r * CDIM + c * 4);
        ((float4*)Qs)[r * 16 + (c ^ (r & 7))] = val;
    }
    __syncthreads();

    const int row = t;
    const int sw  = row & 7;
    float accum[DHEAD];
#pragma unroll
    for (int d = 0; d < DHEAD; d++) accum[d] = 0.f;
    float lsum = 0.f;
    const float scale = 0.125f;  // 1/sqrt(64)

    for (int j = 0; j < LTOK; j++) {
        float s = 0.f;
#pragma unroll
        for (int c = 0; c < 16; c++) {
            float4 qv = ((const float4*)Qs)[row * 16 + (c ^ sw)];
            float4 kv = ((const float4*)Ks)[j * 16 + c];  // broadcast
            s += qv.x * kv.x + qv.y * kv.y + qv.z * kv.z + qv.w * kv.w;
        }
        float e = __expf(s * scale);
        lsum += e;
#pragma unroll
        for (int c = 0; c < 16; c++) {
            float4 vv = ((const float4*)Vs)[j * 16 + c];  // broadcast
            accum[c * 4 + 0] += e * vv.x;
            accum[c * 4 + 1] += e * vv.y;
            accum[c * 4 + 2] += e * vv.z;
            accum[c * 4 + 3] += e * vv.w;
        }
    }

    const float inv = 1.0f / lsum;
    float* obase = o + (size_t)(b * SEQ + s0 + row) * CDIM + h * DHEAD;
#pragma unroll
    for (int c = 0; c < 16; c++) {
        float4 r = make_float4(accum[c * 4 + 0] * inv, accum[c * 4 + 1] * inv,
                               accum[c * 4 + 2] * inv, accum[c * 4 + 3] * inv);
        ((float4*)obase)[c] = r;
    }
}

// ============================================================
// launch
// ============================================================
extern "C" void kernel_launch(void* const* d_in, const int* in_sizes, int n_in,
                              void* d_out, int out_size)
{
    const float* hs  = (const float*)d_in[0];  // [16,4096,1024]
    const float* enc = (const float*)d_in[1];  // [16,77,768]
    const float* Wq  = (const float*)d_in[2];  // [1024,1024]
    const float* Wk  = (const float*)d_in[3];  // [768,1024]
    const float* Wv  = (const float*)d_in[4];  // [768,1024]
    const float* Wo  = (const float*)d_in[5];  // [1024,1024]
    const float* bo  = (const float*)d_in[6];  // [1024]
    float* out = (float*)d_out;
    (void)in_sizes; (void)n_in; (void)out_size;

    float *qb, *kb, *vb, *ab;
    cudaGetSymbolAddress((void**)&qb, g_q);
    cudaGetSymbolAddress((void**)&kb, g_k);
    cudaGetSymbolAddress((void**)&vb, g_v);
    cudaGetSymbolAddress((void**)&ab, g_attn);

    dim3 blk(256);

    // q = hs @ Wq            [65536,1024] x [1024,1024]
    gemm_tf32<<<dim3(CDIM / 128, MQ / 128), blk>>>(hs, Wq, qb, MQ, CDIM, CDIM, nullptr);
    // k = enc @ Wk, v = enc @ Wv   [1232,768] x [768,1024]
    gemm_tf32<<<dim3(CDIM / 128, (MKV + 127) / 128), blk>>>(enc, Wk, kb, MKV, CENC, CDIM, nullptr);
    gemm_tf32<<<dim3(CDIM / 128, (MKV + 127) / 128), blk>>>(enc, Wv, vb, MKV, CENC, CDIM, nullptr);

    // fused attention
    cudaFuncSetAttribute(attn_kernel, cudaFuncAttributeMaxDynamicSharedMemorySize, ATTN_SMEM);
    attn_kernel<<<dim3(SEQ / TILE_S, BATCH * NHEAD), TILE_S, ATTN_SMEM>>>(qb, kb, vb, ab);

    // out = attn @ Wo + bo
    gemm_tf32<<<dim3(CDIM / 128, MQ / 128), blk>>>(ab, Wo, out, MQ, CDIM, CDIM, bo);
}